// round 10
// baseline (speedup 1.0000x reference)
#include <cuda_runtime.h>

// QuantBatchedEmbeddingBag: T=8 tables, R=200000 rows, D=128, B=2048 bags/table.
// Inputs (metadata order):
//   d_in[0] indices     int32 [N = 524288]
//   d_in[1] offsets     int32 [T*B + 1 = 16385]  (CSR bag boundaries, feature-major)
//   d_in[2] qweights    int32 [T, R, D]          (int8 codes in [0,256) stored as int32)
//   d_in[3] scale_shift float32 [T, R, 2]
// Output: float32 [B, T*D] = [2048, 1024], out[b, t*D + d] = pooled[t*B + b, d]

#define T_TABLES 8
#define R_ROWS   200000
#define D_DIM    128
#define B_BATCH  2048
#define NUM_BAGS (T_TABLES * B_BATCH)
#define PIPE     6   // gather pipeline depth (6 x int4 = 24 regs)
#define WPB      4   // warps cooperating per bag
#define BPC      4   // bags per CTA (software-pipelined); 2048 % BPC == 0

__global__ __launch_bounds__(WPB * 32, 10)   // <=51 regs -> 10 CTAs/SM = 40 warps
void embbag_kernel(const int*   __restrict__ indices,
                   const int*   __restrict__ offsets,
                   const int*   __restrict__ qweights,
                   const float* __restrict__ scale_shift,
                   float*       __restrict__ out)
{
    const int bag0 = blockIdx.x * BPC;     // BPC consecutive bags, same table
    const int s    = threadIdx.x >> 5;     // sub-warp id within bag (0..3)
    const int lane = threadIdx.x & 31;

    const int t  = bag0 / B_BATCH;         // table (constant across the BPC bags)
    const int b0 = bag0 % B_BATCH;         // first batch row

    // Per-table bases. Rows are 128 int32 = 512B; each lane reads int4 at lane*16B.
    const int4*   qbase  = reinterpret_cast<const int4*>(
                               qweights + (long long)t * R_ROWS * D_DIM);
    const float2* ssbase = reinterpret_cast<const float2*>(scale_shift)
                               + (long long)t * R_ROWS;

    __shared__ float4 red[WPB][32];

    // ---- Prefetch bag 0 of this CTA ----
    int    pf_start, pf_count, pf_idx;
    float2 pf_ss;
    {
        const int st  = offsets[bag0];
        const int len = offsets[bag0 + 1] - st;
        pf_start = st;
        pf_count = (len > s) ? (len - s + WPB - 1) / WPB : 0;
        const bool pv = lane < pf_count;               // first chunk only
        pf_idx = pv ? __ldg(indices + st + s + WPB * lane) : 0;
        pf_ss  = pv ? __ldg(ssbase + pf_idx) : make_float2(0.f, 0.f);
    }

    for (int i = 0; i < BPC; i++) {
        // Adopt prefetched state for the current bag.
        const int    start = pf_start;
        const int    count = pf_count;
        int          myidx = pf_idx;
        float2       myss  = pf_ss;

        // Issue the NEXT bag's index load now (its latency overlaps the current
        // bag's row gathers). The dependent scale/shift load is deferred until
        // after the row groups so this warp never blocks on pf_idx here.
        bool pf_v = false;
        if (i + 1 < BPC) {
            const int bag = bag0 + i + 1;
            const int st  = offsets[bag];
            const int len = offsets[bag + 1] - st;
            pf_start = st;
            pf_count = (len > s) ? (len - s + WPB - 1) / WPB : 0;
            pf_v     = lane < pf_count;
            pf_idx   = pf_v ? __ldg(indices + st + s + WPB * lane) : 0;
        }

        float4 acc = make_float4(0.f, 0.f, 0.f, 0.f);
        float  shift_sum = 0.f;

        for (int jbase = 0; jbase < count; jbase += 32) {
            const int n = min(32, count - jbase);      // valid lanes are a prefix
            if (jbase > 0) {                           // rare tail chunks (len>128)
                const int  j = jbase + lane;
                const bool v = (j < count);
                myidx = v ? __ldg(indices + start + s + WPB * j) : 0;
                myss  = v ? __ldg(ssbase + myidx) : make_float2(0.f, 0.f);
            }

            // Row gather in groups of PIPE: all PIPE independent LDG.128s issued
            // before any FMA consumes them -> per-warp MLP = PIPE.
            for (int g = 0; g < n; g += PIPE) {
                const int m = min(PIPE, n - g);
                int4 q[PIPE];
                #pragma unroll
                for (int k = 0; k < PIPE; k++) {
                    if (k < m) {
                        const int row = __shfl_sync(0xffffffffu, myidx, g + k);
                        q[k] = __ldg(qbase + (long long)row * (D_DIM / 4) + lane);
                    }
                }
                #pragma unroll
                for (int k = 0; k < PIPE; k++) {
                    if (k < m) {
                        const float sc = __shfl_sync(0xffffffffu, myss.x, g + k);
                        acc.x = fmaf((float)q[k].x, sc, acc.x);
                        acc.y = fmaf((float)q[k].y, sc, acc.y);
                        acc.z = fmaf((float)q[k].z, sc, acc.z);
                        acc.w = fmaf((float)q[k].w, sc, acc.w);
                    }
                }
            }

            // Warp-reduce the shifts once per chunk (invalid lanes contribute 0).
            float sh = myss.y;
            #pragma unroll
            for (int d = 16; d > 0; d >>= 1)
                sh += __shfl_xor_sync(0xffffffffu, sh, d);
            shift_sum += sh;
        }

        // Now the next bag's indices have long since landed: issue its
        // scale/shift gather so it flies during the reduce/store below.
        if (i + 1 < BPC)
            pf_ss = pf_v ? __ldg(ssbase + pf_idx) : make_float2(0.f, 0.f);

        acc.x += shift_sum;
        acc.y += shift_sum;
        acc.z += shift_sum;
        acc.w += shift_sum;

        // Combine the WPB partial accumulators through shared memory.
        red[s][lane] = acc;
        __syncthreads();
        if (s == 0) {
            float4 a0 = red[0][lane];
            float4 a1 = red[1][lane];
            float4 a2 = red[2][lane];
            float4 a3 = red[3][lane];
            a0.x += a1.x + a2.x + a3.x;
            a0.y += a1.y + a2.y + a3.y;
            a0.z += a1.z + a2.z + a3.z;
            a0.w += a1.w + a2.w + a3.w;
            // out[b, t*D + lane*4 .. +3] -> float4 index (b*T + t)*32 + lane
            reinterpret_cast<float4*>(out)[
                ((long long)(b0 + i) * T_TABLES + t) * (D_DIM / 4) + lane] = a0;
        }
        __syncthreads();   // red[] reused next bag
    }
}

extern "C" void kernel_launch(void* const* d_in, const int* in_sizes, int n_in,
                              void* d_out, int out_size)
{
    const int*   indices     = (const int*)  d_in[0];
    const int*   offsets     = (const int*)  d_in[1];
    const int*   qweights    = (const int*)  d_in[2];
    const float* scale_shift = (const float*)d_in[3];
    float*       out         = (float*)      d_out;

    embbag_kernel<<<NUM_BAGS / BPC, WPB * 32>>>(indices, offsets, qweights,
                                                scale_shift, out);
}